// round 10
// baseline (speedup 1.0000x reference)
#include <cuda_runtime.h>

#define D       128
#define N_SRC   200000
#define N_MID   50000
#define N_DST   10000
#define E1      800000
#define E2      160000

typedef unsigned long long u64t;

#define SCAN_CHUNK 2048
#define NB1 ((N_MID + SCAN_CHUNK - 1) / SCAN_CHUNK)   // 25
#define NB2 ((N_DST + SCAN_CHUNK - 1) / SCAN_CHUNK)   // 5

// layer-1 pipeline chunking (multiple of ROWS_PER_BLOCK=64)
#define NCHUNK 4
#define CHUNK_ROWS 12544           // 196 * 64; last chunk = 12368 rows

// ---- scratch (static device globals; no runtime allocation) ----
__device__ int   g_cnt1[N_MID + SCAN_CHUNK];
__device__ int   g_off1[NB1 * SCAN_CHUNK];
__device__ int   g_bsum1[32];                 // RAW per-block totals
__device__ int   g_eidx1[E1];
__device__ int   g_slot1[E1];
__device__ int   g_cnt2[N_DST + SCAN_CHUNK];
__device__ int   g_off2[NB2 * SCAN_CHUNK];
__device__ int   g_bsum2[32];
__device__ int   g_eidx2[E2];
__device__ int   g_slot2[E2];
__device__ float g_agg[N_MID * D];
__device__ float g_h[N_MID * D];

// ---------------------------------------------------------------------
__global__ void zero_all(int* c1, int n1, int* c2, int n2) {
    int i = blockIdx.x * blockDim.x + threadIdx.x;
    if (i < n1) c1[i] = 0;
    if (i < n2) c2[i] = 0;
}

// Histogram + slot assignment in one pass (1 edge/thread).
__global__ void hist_slot(const int* __restrict__ col,
                          int* __restrict__ cnt,
                          int* __restrict__ slot, int E) {
    int i = blockIdx.x * blockDim.x + threadIdx.x;
    if (i < E) slot[i] = atomicAdd(&cnt[col[i]], 1);
}

// Per-block scan of SCAN_CHUNK counts; off[] = within-block exclusive
// prefixes, bsum[b] = RAW block total.
__global__ void __launch_bounds__(256, 4)
scan_partial(const int* __restrict__ cnt, int* __restrict__ off,
             int* __restrict__ bsum) {
    __shared__ int wsum[8];
    const int t = threadIdx.x, lane = t & 31, w = t >> 5;
    const int base = blockIdx.x * SCAN_CHUNK + t * 8;

    int4 a = *(const int4*)(cnt + base);
    int4 b = *(const int4*)(cnt + base + 4);
    int v[8] = {a.x, a.y, a.z, a.w, b.x, b.y, b.z, b.w};
    int s = 0;
    #pragma unroll
    for (int j = 0; j < 8; j++) s += v[j];

    int x = s;
    #pragma unroll
    for (int d = 1; d < 32; d <<= 1) {
        int y = __shfl_up_sync(0xffffffffu, x, d);
        if (lane >= d) x += y;
    }
    if (lane == 31) wsum[w] = x;
    __syncthreads();
    if (t < 8) {
        int ws = wsum[t];
        int p = 0;
        #pragma unroll
        for (int q = 0; q < 8; q++) {
            int val = __shfl_sync(0xffu, ws, q);
            if (q < t) p += val;
        }
        wsum[t] = p;
    }
    __syncthreads();

    int run = (x - s) + wsum[w];
    int o[8];
    #pragma unroll
    for (int j = 0; j < 8; j++) { o[j] = run; run += v[j]; }
    *(int4*)(off + base)     = make_int4(o[0], o[1], o[2], o[3]);
    *(int4*)(off + base + 4) = make_int4(o[4], o[5], o[6], o[7]);
    if (t == 255) bsum[blockIdx.x] = run;
}

// Per-warp register scan of raw block totals -> lane's exclusive prefix.
__device__ __forceinline__ int warp_bsum_excl(const int* __restrict__ bsum,
                                              int nb) {
    int lane = threadIdx.x & 31;
    int v = (lane < nb) ? bsum[lane] : 0;
    int x = v;
    #pragma unroll
    for (int d = 1; d < 32; d <<= 1) {
        int y = __shfl_up_sync(0xffffffffu, x, d);
        if (lane >= d) x += y;
    }
    return x - v;
}

// Placement: pure scatter, 1 edge/thread, no atomics.
__global__ void place_scatter(const int* __restrict__ row,
                              const int* __restrict__ col,
                              const int* __restrict__ slot,
                              const int* __restrict__ off,
                              const int* __restrict__ bsum, int nb,
                              int* __restrict__ eidx, int E) {
    int excl = warp_bsum_excl(bsum, nb);
    int i = blockIdx.x * blockDim.x + threadIdx.x;
    if (i < E) {
        int c = col[i];
        int base = off[c] + __shfl_sync(0xffffffffu, excl, c >> 11);
        eidx[base + slot[i]] = row[i];
    }
}

// ---------------------------------------------------------------------
// Aggregation over row range [c0, c1): one warp per destination row.
// ---------------------------------------------------------------------
__global__ void __launch_bounds__(256)
agg_kernel(const float* __restrict__ xsrc,
           const int* __restrict__ off,
           const int* __restrict__ bsum, int nb,
           const int* __restrict__ eidx,
           float* __restrict__ agg, int c0, int c1) {
    const int excl = warp_bsum_excl(bsum, nb);
    int c    = c0 + ((blockIdx.x * blockDim.x + threadIdx.x) >> 5);
    int lane = threadIdx.x & 31;
    if (c >= c1) return;
    int s = off[c]     + __shfl_sync(0xffffffffu, excl, c >> 11);
    int e = off[c + 1] + __shfl_sync(0xffffffffu, excl, (c + 1) >> 11);

    float4 acc = make_float4(0.f, 0.f, 0.f, 0.f);
    int i = s;
    for (; i + 4 <= e; i += 4) {
        int r0 = eidx[i + 0], r1 = eidx[i + 1];
        int r2 = eidx[i + 2], r3 = eidx[i + 3];
        float4 v0 = ((const float4*)(xsrc + (size_t)r0 * D))[lane];
        float4 v1 = ((const float4*)(xsrc + (size_t)r1 * D))[lane];
        float4 v2 = ((const float4*)(xsrc + (size_t)r2 * D))[lane];
        float4 v3 = ((const float4*)(xsrc + (size_t)r3 * D))[lane];
        acc.x += (v0.x + v1.x) + (v2.x + v3.x);
        acc.y += (v0.y + v1.y) + (v2.y + v3.y);
        acc.z += (v0.z + v1.z) + (v2.z + v3.z);
        acc.w += (v0.w + v1.w) + (v2.w + v3.w);
    }
    for (; i < e; i++) {
        int r = eidx[i];
        float4 v = ((const float4*)(xsrc + (size_t)r * D))[lane];
        acc.x += v.x; acc.y += v.y; acc.z += v.z; acc.w += v.w;
    }
    float invd = (e > s) ? 1.0f / (float)(e - s) : 0.f;
    acc.x *= invd; acc.y *= invd; acc.z *= invd; acc.w *= invd;
    ((float4*)(agg + (size_t)c * D))[lane] = acc;
}

// ---------------------------------------------------------------------
// SAGE finish with f32x2 FMA (R3-proven), over rows starting rowStart.
// ---------------------------------------------------------------------
#define KS 132
#define RPW 8
#define ROWS_PER_BLOCK 64
#define SAGE_SMEM_BYTES ((KS * D + D + ROWS_PER_BLOCK * D) * 4)

__device__ __forceinline__ u64t pack2(float a) {
    u64t r;
    unsigned ai = __float_as_uint(a);
    asm("mov.b64 %0, {%1, %1};" : "=l"(r) : "r"(ai));
    return r;
}
__device__ __forceinline__ void ffma2(u64t& d, u64t a, u64t b) {
    asm("fma.rn.f32x2 %0, %1, %2, %3;" : "=l"(d) : "l"(a), "l"(b), "l"(d));
}

template <bool RELU>
__global__ void __launch_bounds__(256, 2)
sage_kernel(const float* __restrict__ agg,
            const float* __restrict__ xdst,
            const float* __restrict__ Wl, const float* __restrict__ bl,
            const float* __restrict__ Wr,
            float* __restrict__ out, int rowStart, int n) {
    extern __shared__ float smem[];
    float* sW  = smem;                    // KS * 128 transposed (reused)
    float* sb  = smem + KS * D;           // 128
    float* sIn = sb + D;                  // 64 * 128 staging

    const int tid  = threadIdx.x;
    const int lane = tid & 31;
    const int warp = tid >> 5;
    const int l4   = lane * 4;

    for (int idx = tid; idx < D * D; idx += 256) {
        int j = idx >> 7, k = idx & (D - 1);
        sW[k * KS + j] = Wl[idx];
    }
    if (tid < D) sb[tid] = bl[tid];

    float* myIn = sIn + warp * (RPW * D);
    const int rowBase = rowStart + blockIdx.x * ROWS_PER_BLOCK + warp * RPW;

    #pragma unroll
    for (int r = 0; r < RPW; r++) {
        int row = rowBase + r;
        float4 v = make_float4(0.f, 0.f, 0.f, 0.f);
        if (row < n) v = ((const float4*)(agg + (size_t)row * D))[lane];
        ((float4*)(myIn + r * D))[lane] = v;
    }
    __syncthreads();

    u64t acc[RPW][2];
    {
        u64t b0 = *(const u64t*)&sb[l4];
        u64t b1 = *(const u64t*)&sb[l4 + 2];
        #pragma unroll
        for (int r = 0; r < RPW; r++) { acc[r][0] = b0; acc[r][1] = b1; }
    }

    // ---- phase A: mean @ Wl^T ----
    #pragma unroll 4
    for (int k = 0; k < D; k++) {
        ulonglong2 w = *(const ulonglong2*)&sW[k * KS + l4];
        #pragma unroll
        for (int r = 0; r < RPW; r++) {
            u64t a = pack2(myIn[r * D + k]);
            ffma2(acc[r][0], a, w.x);
            ffma2(acc[r][1], a, w.y);
        }
    }
    __syncthreads();

    // reload buffer with Wr; restage xdst
    for (int idx = tid; idx < D * D; idx += 256) {
        int j = idx >> 7, k = idx & (D - 1);
        sW[k * KS + j] = Wr[idx];
    }
    #pragma unroll
    for (int r = 0; r < RPW; r++) {
        int row = rowBase + r;
        float4 v = make_float4(0.f, 0.f, 0.f, 0.f);
        if (row < n) v = ((const float4*)(xdst + (size_t)row * D))[lane];
        ((float4*)(myIn + r * D))[lane] = v;
    }
    __syncthreads();

    // ---- phase B: + xdst @ Wr^T ----
    #pragma unroll 4
    for (int k = 0; k < D; k++) {
        ulonglong2 w = *(const ulonglong2*)&sW[k * KS + l4];
        #pragma unroll
        for (int r = 0; r < RPW; r++) {
            u64t a = pack2(myIn[r * D + k]);
            ffma2(acc[r][0], a, w.x);
            ffma2(acc[r][1], a, w.y);
        }
    }

    // ---- L2-normalize, (ReLU), store ----
    union F2 { u64t u; float2 f; };
    #pragma unroll
    for (int r = 0; r < RPW; r++) {
        int row = rowBase + r;
        F2 a0, a1; a0.u = acc[r][0]; a1.u = acc[r][1];
        float o0 = a0.f.x, o1 = a0.f.y, o2 = a1.f.x, o3 = a1.f.y;
        float s = o0 * o0 + o1 * o1 + o2 * o2 + o3 * o3;
        #pragma unroll
        for (int d = 16; d > 0; d >>= 1)
            s += __shfl_xor_sync(0xFFFFFFFFu, s, d);
        float inv = 1.0f / fmaxf(sqrtf(s), 1e-12f);
        o0 *= inv; o1 *= inv; o2 *= inv; o3 *= inv;
        if (RELU) {
            o0 = fmaxf(o0, 0.f); o1 = fmaxf(o1, 0.f);
            o2 = fmaxf(o2, 0.f); o3 = fmaxf(o3, 0.f);
        }
        if (row < n)
            ((float4*)(out + (size_t)row * D))[lane] = make_float4(o0, o1, o2, o3);
    }
}

// ---------------------------------------------------------------------
// Launch sequence — R9 structure + chunked agg1/sage1 pipeline.
// ---------------------------------------------------------------------
extern "C" void kernel_launch(void* const* d_in, const int* in_sizes, int n_in,
                              void* d_out, int out_size) {
    const float* x    = (const float*)d_in[0];
    const float* Wl1  = (const float*)d_in[1];
    const float* bl1  = (const float*)d_in[2];
    const float* Wr1  = (const float*)d_in[3];
    const float* Wl2  = (const float*)d_in[4];
    const float* bl2  = (const float*)d_in[5];
    const float* Wr2  = (const float*)d_in[6];
    const int*   row1 = (const int*)d_in[7];
    const int*   col1 = (const int*)d_in[8];
    const int*   row2 = (const int*)d_in[9];
    const int*   col2 = (const int*)d_in[10];
    float* out = (float*)d_out;

    int *cnt1, *off1, *bsum1, *eidx1, *slot1;
    int *cnt2, *off2, *bsum2, *eidx2, *slot2;
    float *agg, *h;
    cudaGetSymbolAddress((void**)&cnt1, g_cnt1);
    cudaGetSymbolAddress((void**)&off1, g_off1);
    cudaGetSymbolAddress((void**)&bsum1, g_bsum1);
    cudaGetSymbolAddress((void**)&eidx1, g_eidx1);
    cudaGetSymbolAddress((void**)&slot1, g_slot1);
    cudaGetSymbolAddress((void**)&cnt2, g_cnt2);
    cudaGetSymbolAddress((void**)&off2, g_off2);
    cudaGetSymbolAddress((void**)&bsum2, g_bsum2);
    cudaGetSymbolAddress((void**)&eidx2, g_eidx2);
    cudaGetSymbolAddress((void**)&slot2, g_slot2);
    cudaGetSymbolAddress((void**)&agg, g_agg);
    cudaGetSymbolAddress((void**)&h,   g_h);

    cudaFuncSetAttribute(sage_kernel<true>,
                         cudaFuncAttributeMaxDynamicSharedMemorySize, SAGE_SMEM_BYTES);
    cudaFuncSetAttribute(sage_kernel<false>,
                         cudaFuncAttributeMaxDynamicSharedMemorySize, SAGE_SMEM_BYTES);

    static cudaStream_t s_side = nullptr, s_aggs = nullptr;
    static cudaEvent_t  s_ev0 = nullptr, s_ev1 = nullptr, s_evP = nullptr;
    static cudaEvent_t  s_evA[NCHUNK] = {};
    if (!s_side) {
        cudaStreamCreateWithFlags(&s_side, cudaStreamNonBlocking);
        cudaStreamCreateWithFlags(&s_aggs, cudaStreamNonBlocking);
        cudaEventCreateWithFlags(&s_ev0, cudaEventDisableTiming);
        cudaEventCreateWithFlags(&s_ev1, cudaEventDisableTiming);
        cudaEventCreateWithFlags(&s_evP, cudaEventDisableTiming);
        for (int c = 0; c < NCHUNK; c++)
            cudaEventCreateWithFlags(&s_evA[c], cudaEventDisableTiming);
    }

    // zero both count arrays (padded) in one kernel (main stream)
    {
        int nmax = N_MID + SCAN_CHUNK;
        zero_all<<<(nmax + 255) / 256, 256>>>(cnt1, N_MID + SCAN_CHUNK,
                                              cnt2, N_DST + SCAN_CHUNK);
    }

    // ---- fork: CSR2 build on side stream ----
    cudaEventRecord(s_ev0, 0);
    cudaStreamWaitEvent(s_side, s_ev0, 0);
    hist_slot<<<(E2 + 255) / 256, 256, 0, s_side>>>(col2, cnt2, slot2, E2);
    scan_partial<<<NB2, 256, 0, s_side>>>(cnt2, off2, bsum2);
    place_scatter<<<(E2 + 255) / 256, 256, 0, s_side>>>(row2, col2, slot2,
                                                        off2, bsum2, NB2,
                                                        eidx2, E2);
    cudaEventRecord(s_ev1, s_side);

    // ---- main: CSR1 build ----
    hist_slot<<<(E1 + 255) / 256, 256>>>(col1, cnt1, slot1, E1);
    scan_partial<<<NB1, 256>>>(cnt1, off1, bsum1);
    place_scatter<<<(E1 + 255) / 256, 256>>>(row1, col1, slot1,
                                             off1, bsum1, NB1, eidx1, E1);

    // ---- layer 1: chunked agg (s_aggs) pipelined with sage (main) ----
    cudaEventRecord(s_evP, 0);
    cudaStreamWaitEvent(s_aggs, s_evP, 0);
    for (int c = 0; c < NCHUNK; c++) {
        int c0 = c * CHUNK_ROWS;
        int c1 = (c0 + CHUNK_ROWS < N_MID) ? c0 + CHUNK_ROWS : N_MID;
        int rows = c1 - c0;
        agg_kernel<<<(rows * 32 + 255) / 256, 256, 0, s_aggs>>>(
            x, off1, bsum1, NB1, eidx1, agg, c0, c1);
        cudaEventRecord(s_evA[c], s_aggs);
    }
    for (int c = 0; c < NCHUNK; c++) {
        int c0 = c * CHUNK_ROWS;
        int c1 = (c0 + CHUNK_ROWS < N_MID) ? c0 + CHUNK_ROWS : N_MID;
        int rows = c1 - c0;
        cudaStreamWaitEvent(0, s_evA[c], 0);
        sage_kernel<true><<<(rows + ROWS_PER_BLOCK - 1) / ROWS_PER_BLOCK, 256,
                            SAGE_SMEM_BYTES>>>(agg, x, Wl1, bl1, Wr1, h,
                                               c0, N_MID);
    }

    // ---- join CSR2, layer 2 ----
    cudaStreamWaitEvent(0, s_ev1, 0);
    agg_kernel<<<(N_DST * 32 + 255) / 256, 256>>>(h, off2, bsum2, NB2,
                                                  eidx2, agg, 0, N_DST);
    sage_kernel<false><<<(N_DST + ROWS_PER_BLOCK - 1) / ROWS_PER_BLOCK, 256,
                         SAGE_SMEM_BYTES>>>(agg, h, Wl2, bl2, Wr2, out,
                                            0, N_DST);
}

// round 11
// speedup vs baseline: 1.0907x; 1.0907x over previous
#include <cuda_runtime.h>

#define D       128
#define N_SRC   200000
#define N_MID   50000
#define N_DST   10000
#define E1      800000
#define E2      160000

typedef unsigned long long u64t;

#define SCAN_CHUNK 2048
#define NB1 ((N_MID + SCAN_CHUNK - 1) / SCAN_CHUNK)   // 25
#define NB2 ((N_DST + SCAN_CHUNK - 1) / SCAN_CHUNK)   // 5

// ---- scratch (static device globals; no runtime allocation) ----
__device__ int   g_cnt1[N_MID + SCAN_CHUNK];
__device__ int   g_off1[NB1 * SCAN_CHUNK];
__device__ int   g_bsum1[32];                 // RAW per-block totals
__device__ int   g_eidx1[E1];
__device__ int   g_slot1[E1];
__device__ int   g_cnt2[N_DST + SCAN_CHUNK];
__device__ int   g_off2[NB2 * SCAN_CHUNK];
__device__ int   g_bsum2[32];
__device__ int   g_eidx2[E2];
__device__ int   g_slot2[E2];
__device__ float g_agg[N_MID * D];
__device__ float g_h[N_MID * D];

// ---------------------------------------------------------------------
__global__ void zero_all(int* c1, int n1, int* c2, int n2) {
    int i = blockIdx.x * blockDim.x + threadIdx.x;
    if (i < n1) c1[i] = 0;
    if (i < n2) c2[i] = 0;
}

// Histogram + slot assignment in one pass (1 edge/thread).
__global__ void hist_slot(const int* __restrict__ col,
                          int* __restrict__ cnt,
                          int* __restrict__ slot, int E) {
    int i = blockIdx.x * blockDim.x + threadIdx.x;
    if (i < E) slot[i] = atomicAdd(&cnt[col[i]], 1);
}

// Per-block scan of SCAN_CHUNK counts; off[] = within-block exclusive
// prefixes, bsum[b] = RAW block total.
__global__ void __launch_bounds__(256, 4)
scan_partial(const int* __restrict__ cnt, int* __restrict__ off,
             int* __restrict__ bsum) {
    __shared__ int wsum[8];
    const int t = threadIdx.x, lane = t & 31, w = t >> 5;
    const int base = blockIdx.x * SCAN_CHUNK + t * 8;

    int4 a = *(const int4*)(cnt + base);
    int4 b = *(const int4*)(cnt + base + 4);
    int v[8] = {a.x, a.y, a.z, a.w, b.x, b.y, b.z, b.w};
    int s = 0;
    #pragma unroll
    for (int j = 0; j < 8; j++) s += v[j];

    int x = s;
    #pragma unroll
    for (int d = 1; d < 32; d <<= 1) {
        int y = __shfl_up_sync(0xffffffffu, x, d);
        if (lane >= d) x += y;
    }
    if (lane == 31) wsum[w] = x;
    __syncthreads();
    if (t < 8) {
        int ws = wsum[t];
        int p = 0;
        #pragma unroll
        for (int q = 0; q < 8; q++) {
            int val = __shfl_sync(0xffu, ws, q);
            if (q < t) p += val;
        }
        wsum[t] = p;
    }
    __syncthreads();

    int run = (x - s) + wsum[w];
    int o[8];
    #pragma unroll
    for (int j = 0; j < 8; j++) { o[j] = run; run += v[j]; }
    *(int4*)(off + base)     = make_int4(o[0], o[1], o[2], o[3]);
    *(int4*)(off + base + 4) = make_int4(o[4], o[5], o[6], o[7]);
    if (t == 255) bsum[blockIdx.x] = run;
}

// Per-warp register scan of raw block totals -> lane's exclusive prefix.
__device__ __forceinline__ int warp_bsum_excl(const int* __restrict__ bsum,
                                              int nb) {
    int lane = threadIdx.x & 31;
    int v = (lane < nb) ? bsum[lane] : 0;
    int x = v;
    #pragma unroll
    for (int d = 1; d < 32; d <<= 1) {
        int y = __shfl_up_sync(0xffffffffu, x, d);
        if (lane >= d) x += y;
    }
    return x - v;
}

// Placement: pure scatter, 1 edge/thread, no atomics.
__global__ void place_scatter(const int* __restrict__ row,
                              const int* __restrict__ col,
                              const int* __restrict__ slot,
                              const int* __restrict__ off,
                              const int* __restrict__ bsum, int nb,
                              int* __restrict__ eidx, int E) {
    int excl = warp_bsum_excl(bsum, nb);
    int i = blockIdx.x * blockDim.x + threadIdx.x;
    if (i < E) {
        int c = col[i];
        int base = off[c] + __shfl_sync(0xffffffffu, excl, c >> 11);
        eidx[base + slot[i]] = row[i];
    }
}

// ---------------------------------------------------------------------
// Aggregation: one warp per destination row; 4-edge unrolled gather.
// ---------------------------------------------------------------------
__global__ void __launch_bounds__(256)
agg_kernel(const float* __restrict__ xsrc,
           const int* __restrict__ off,
           const int* __restrict__ bsum, int nb,
           const int* __restrict__ eidx,
           float* __restrict__ agg, int n) {
    const int excl = warp_bsum_excl(bsum, nb);
    int c    = (blockIdx.x * blockDim.x + threadIdx.x) >> 5;
    int lane = threadIdx.x & 31;
    if (c >= n) return;
    int s = off[c]     + __shfl_sync(0xffffffffu, excl, c >> 11);
    int e = off[c + 1] + __shfl_sync(0xffffffffu, excl, (c + 1) >> 11);

    float4 acc = make_float4(0.f, 0.f, 0.f, 0.f);
    int i = s;
    for (; i + 4 <= e; i += 4) {
        int r0 = eidx[i + 0], r1 = eidx[i + 1];
        int r2 = eidx[i + 2], r3 = eidx[i + 3];
        float4 v0 = ((const float4*)(xsrc + (size_t)r0 * D))[lane];
        float4 v1 = ((const float4*)(xsrc + (size_t)r1 * D))[lane];
        float4 v2 = ((const float4*)(xsrc + (size_t)r2 * D))[lane];
        float4 v3 = ((const float4*)(xsrc + (size_t)r3 * D))[lane];
        acc.x += (v0.x + v1.x) + (v2.x + v3.x);
        acc.y += (v0.y + v1.y) + (v2.y + v3.y);
        acc.z += (v0.z + v1.z) + (v2.z + v3.z);
        acc.w += (v0.w + v1.w) + (v2.w + v3.w);
    }
    for (; i < e; i++) {
        int r = eidx[i];
        float4 v = ((const float4*)(xsrc + (size_t)r * D))[lane];
        acc.x += v.x; acc.y += v.y; acc.z += v.z; acc.w += v.w;
    }
    float invd = (e > s) ? 1.0f / (float)(e - s) : 0.f;
    acc.x *= invd; acc.y *= invd; acc.z *= invd; acc.w *= invd;
    ((float4*)(agg + (size_t)c * D))[lane] = acc;
}

// ---------------------------------------------------------------------
// SAGE finish, issue-slot optimized (R5 variant, isolated this round):
// staging TRANSPOSED into row-pairs myT[k*PADK + r] so per k per warp:
// 16 FFMA2 + 8 MOV(pack2 of w) + 4 LDS.64 + 1 LDS.128 = 29 issue slots
// < 32 -> FMA-pipe bound at 2 CTAs/SM. Weights transposed in-kernel
// into KS-padded smem exactly as the proven R3/R9 kernel does.
// ---------------------------------------------------------------------
#define KS 132
#define PADK 10                      // even -> 8B-aligned row pairs
#define ROWS_PER_BLOCK 64
#define SAGE_SMEM_BYTES ((KS * D + D + 8 * D * PADK) * 4)

__device__ __forceinline__ u64t pack2(float a) {
    u64t r;
    unsigned ai = __float_as_uint(a);
    asm("mov.b64 %0, {%1, %1};" : "=l"(r) : "r"(ai));
    return r;
}
__device__ __forceinline__ void ffma2(u64t& d, u64t a, u64t b) {
    asm("fma.rn.f32x2 %0, %1, %2, %3;" : "=l"(d) : "l"(a), "l"(b), "l"(d));
}

template <bool RELU>
__global__ void __launch_bounds__(256, 2)
sage_kernel(const float* __restrict__ agg,
            const float* __restrict__ xdst,
            const float* __restrict__ Wl, const float* __restrict__ bl,
            const float* __restrict__ Wr,
            float* __restrict__ out, int n) {
    extern __shared__ float smem[];
    float* sW   = smem;                    // KS * 128 transposed (reused)
    float* sb   = smem + KS * D;           // 128
    float* sInT = sb + D;                  // 8 warps * 128 * PADK

    const int tid  = threadIdx.x;
    const int lane = tid & 31;
    const int warp = tid >> 5;
    const int l4   = lane * 4;

    for (int idx = tid; idx < D * D; idx += 256) {
        int j = idx >> 7, k = idx & (D - 1);
        sW[k * KS + j] = Wl[idx];
    }
    if (tid < D) sb[tid] = bl[tid];

    float* myT = sInT + warp * (D * PADK);
    const int rowBase = blockIdx.x * ROWS_PER_BLOCK + warp * 8;

    // ---- stage mean rows TRANSPOSED: myT[k*PADK + r] ----
    #pragma unroll
    for (int r = 0; r < 8; r++) {
        int row = rowBase + r;
        float4 v = make_float4(0.f, 0.f, 0.f, 0.f);
        if (row < n) v = ((const float4*)(agg + (size_t)row * D))[lane];
        myT[(l4 + 0) * PADK + r] = v.x;
        myT[(l4 + 1) * PADK + r] = v.y;
        myT[(l4 + 2) * PADK + r] = v.z;
        myT[(l4 + 3) * PADK + r] = v.w;
    }
    __syncthreads();

    // acc[p][j] = {out_row(2p)[l4+j], out_row(2p+1)[l4+j]}
    u64t acc[4][4];
    {
        u64t b0 = pack2(sb[l4 + 0]);
        u64t b1 = pack2(sb[l4 + 1]);
        u64t b2 = pack2(sb[l4 + 2]);
        u64t b3 = pack2(sb[l4 + 3]);
        #pragma unroll
        for (int p = 0; p < 4; p++) {
            acc[p][0] = b0; acc[p][1] = b1; acc[p][2] = b2; acc[p][3] = b3;
        }
    }

    // ---- phase A: mean @ Wl^T ----
    #pragma unroll 4
    for (int k = 0; k < D; k++) {
        float4 w = *(const float4*)&sW[k * KS + l4];
        u64t wd0 = pack2(w.x), wd1 = pack2(w.y);
        u64t wd2 = pack2(w.z), wd3 = pack2(w.w);
        const u64t* ak = (const u64t*)&myT[k * PADK];
        u64t a0 = ak[0], a1 = ak[1], a2 = ak[2], a3 = ak[3];
        ffma2(acc[0][0], a0, wd0); ffma2(acc[0][1], a0, wd1);
        ffma2(acc[0][2], a0, wd2); ffma2(acc[0][3], a0, wd3);
        ffma2(acc[1][0], a1, wd0); ffma2(acc[1][1], a1, wd1);
        ffma2(acc[1][2], a1, wd2); ffma2(acc[1][3], a1, wd3);
        ffma2(acc[2][0], a2, wd0); ffma2(acc[2][1], a2, wd1);
        ffma2(acc[2][2], a2, wd2); ffma2(acc[2][3], a2, wd3);
        ffma2(acc[3][0], a3, wd0); ffma2(acc[3][1], a3, wd1);
        ffma2(acc[3][2], a3, wd2); ffma2(acc[3][3], a3, wd3);
    }
    __syncthreads();

    // reload Wr; restage xdst transposed
    for (int idx = tid; idx < D * D; idx += 256) {
        int j = idx >> 7, k = idx & (D - 1);
        sW[k * KS + j] = Wr[idx];
    }
    #pragma unroll
    for (int r = 0; r < 8; r++) {
        int row = rowBase + r;
        float4 v = make_float4(0.f, 0.f, 0.f, 0.f);
        if (row < n) v = ((const float4*)(xdst + (size_t)row * D))[lane];
        myT[(l4 + 0) * PADK + r] = v.x;
        myT[(l4 + 1) * PADK + r] = v.y;
        myT[(l4 + 2) * PADK + r] = v.z;
        myT[(l4 + 3) * PADK + r] = v.w;
    }
    __syncthreads();

    // ---- phase B: + xdst @ Wr^T ----
    #pragma unroll 4
    for (int k = 0; k < D; k++) {
        float4 w = *(const float4*)&sW[k * KS + l4];
        u64t wd0 = pack2(w.x), wd1 = pack2(w.y);
        u64t wd2 = pack2(w.z), wd3 = pack2(w.w);
        const u64t* ak = (const u64t*)&myT[k * PADK];
        u64t a0 = ak[0], a1 = ak[1], a2 = ak[2], a3 = ak[3];
        ffma2(acc[0][0], a0, wd0); ffma2(acc[0][1], a0, wd1);
        ffma2(acc[0][2], a0, wd2); ffma2(acc[0][3], a0, wd3);
        ffma2(acc[1][0], a1, wd0); ffma2(acc[1][1], a1, wd1);
        ffma2(acc[1][2], a1, wd2); ffma2(acc[1][3], a1, wd3);
        ffma2(acc[2][0], a2, wd0); ffma2(acc[2][1], a2, wd1);
        ffma2(acc[2][2], a2, wd2); ffma2(acc[2][3], a2, wd3);
        ffma2(acc[3][0], a3, wd0); ffma2(acc[3][1], a3, wd1);
        ffma2(acc[3][2], a3, wd2); ffma2(acc[3][3], a3, wd3);
    }

    // ---- L2-normalize, (ReLU), store (two rows per pair p) ----
    union F2 { u64t u; float2 f; };
    #pragma unroll
    for (int p = 0; p < 4; p++) {
        F2 c0, c1, c2, c3;
        c0.u = acc[p][0]; c1.u = acc[p][1];
        c2.u = acc[p][2]; c3.u = acc[p][3];
        #pragma unroll
        for (int half = 0; half < 2; half++) {
            int row = rowBase + 2 * p + half;
            float o0 = half ? c0.f.y : c0.f.x;
            float o1 = half ? c1.f.y : c1.f.x;
            float o2 = half ? c2.f.y : c2.f.x;
            float o3 = half ? c3.f.y : c3.f.x;
            float s = o0 * o0 + o1 * o1 + o2 * o2 + o3 * o3;
            #pragma unroll
            for (int d = 16; d > 0; d >>= 1)
                s += __shfl_xor_sync(0xFFFFFFFFu, s, d);
            float inv = 1.0f / fmaxf(sqrtf(s), 1e-12f);
            o0 *= inv; o1 *= inv; o2 *= inv; o3 *= inv;
            if (RELU) {
                o0 = fmaxf(o0, 0.f); o1 = fmaxf(o1, 0.f);
                o2 = fmaxf(o2, 0.f); o3 = fmaxf(o3, 0.f);
            }
            if (row < n)
                ((float4*)(out + (size_t)row * D))[lane] =
                    make_float4(o0, o1, o2, o3);
        }
    }
}

// ---------------------------------------------------------------------
// Launch sequence — EXACT R9 structure (proven 209.3 µs): zero_all up
// front, fork CSR2 at start on normal-priority side stream, one join.
// ---------------------------------------------------------------------
extern "C" void kernel_launch(void* const* d_in, const int* in_sizes, int n_in,
                              void* d_out, int out_size) {
    const float* x    = (const float*)d_in[0];
    const float* Wl1  = (const float*)d_in[1];
    const float* bl1  = (const float*)d_in[2];
    const float* Wr1  = (const float*)d_in[3];
    const float* Wl2  = (const float*)d_in[4];
    const float* bl2  = (const float*)d_in[5];
    const float* Wr2  = (const float*)d_in[6];
    const int*   row1 = (const int*)d_in[7];
    const int*   col1 = (const int*)d_in[8];
    const int*   row2 = (const int*)d_in[9];
    const int*   col2 = (const int*)d_in[10];
    float* out = (float*)d_out;

    int *cnt1, *off1, *bsum1, *eidx1, *slot1;
    int *cnt2, *off2, *bsum2, *eidx2, *slot2;
    float *agg, *h;
    cudaGetSymbolAddress((void**)&cnt1, g_cnt1);
    cudaGetSymbolAddress((void**)&off1, g_off1);
    cudaGetSymbolAddress((void**)&bsum1, g_bsum1);
    cudaGetSymbolAddress((void**)&eidx1, g_eidx1);
    cudaGetSymbolAddress((void**)&slot1, g_slot1);
    cudaGetSymbolAddress((void**)&cnt2, g_cnt2);
    cudaGetSymbolAddress((void**)&off2, g_off2);
    cudaGetSymbolAddress((void**)&bsum2, g_bsum2);
    cudaGetSymbolAddress((void**)&eidx2, g_eidx2);
    cudaGetSymbolAddress((void**)&slot2, g_slot2);
    cudaGetSymbolAddress((void**)&agg, g_agg);
    cudaGetSymbolAddress((void**)&h,   g_h);

    cudaFuncSetAttribute(sage_kernel<true>,
                         cudaFuncAttributeMaxDynamicSharedMemorySize, SAGE_SMEM_BYTES);
    cudaFuncSetAttribute(sage_kernel<false>,
                         cudaFuncAttributeMaxDynamicSharedMemorySize, SAGE_SMEM_BYTES);

    static cudaStream_t s_side = nullptr;
    static cudaEvent_t  s_ev0  = nullptr, s_ev1 = nullptr;
    if (!s_side) {
        cudaStreamCreateWithFlags(&s_side, cudaStreamNonBlocking);
        cudaEventCreateWithFlags(&s_ev0, cudaEventDisableTiming);
        cudaEventCreateWithFlags(&s_ev1, cudaEventDisableTiming);
    }

    // zero both count arrays (padded) in one kernel (main stream)
    {
        int nmax = N_MID + SCAN_CHUNK;
        zero_all<<<(nmax + 255) / 256, 256>>>(cnt1, N_MID + SCAN_CHUNK,
                                              cnt2, N_DST + SCAN_CHUNK);
    }

    // ---- fork: CSR2 build on side stream ----
    cudaEventRecord(s_ev0, 0);
    cudaStreamWaitEvent(s_side, s_ev0, 0);
    hist_slot<<<(E2 + 255) / 256, 256, 0, s_side>>>(col2, cnt2, slot2, E2);
    scan_partial<<<NB2, 256, 0, s_side>>>(cnt2, off2, bsum2);
    place_scatter<<<(E2 + 255) / 256, 256, 0, s_side>>>(row2, col2, slot2,
                                                        off2, bsum2, NB2,
                                                        eidx2, E2);
    cudaEventRecord(s_ev1, s_side);

    // ---- main: CSR1 build + layer 1 ----
    hist_slot<<<(E1 + 255) / 256, 256>>>(col1, cnt1, slot1, E1);
    scan_partial<<<NB1, 256>>>(cnt1, off1, bsum1);
    place_scatter<<<(E1 + 255) / 256, 256>>>(row1, col1, slot1,
                                             off1, bsum1, NB1, eidx1, E1);
    agg_kernel<<<(N_MID * 32 + 255) / 256, 256>>>(x, off1, bsum1, NB1,
                                                  eidx1, agg, N_MID);
    sage_kernel<true><<<(N_MID + ROWS_PER_BLOCK - 1) / ROWS_PER_BLOCK, 256,
                        SAGE_SMEM_BYTES>>>(agg, x, Wl1, bl1, Wr1, h, N_MID);

    // ---- join, layer 2 ----
    cudaStreamWaitEvent(0, s_ev1, 0);
    agg_kernel<<<(N_DST * 32 + 255) / 256, 256>>>(h, off2, bsum2, NB2,
                                                  eidx2, agg, N_DST);
    sage_kernel<false><<<(N_DST + ROWS_PER_BLOCK - 1) / ROWS_PER_BLOCK, 256,
                         SAGE_SMEM_BYTES>>>(agg, h, Wl2, bl2, Wr2, out, N_DST);
}

// round 14
// speedup vs baseline: 1.4519x; 1.3312x over previous
#include <cuda_runtime.h>
#include <cuda_bf16.h>
#include <cstdint>

#define D       128
#define N_SRC   200000
#define N_MID   50000
#define N_DST   10000
#define E1      800000
#define E2      160000

typedef unsigned long long u64t;

#define SCAN_CHUNK 2048
#define NB1 ((N_MID + SCAN_CHUNK - 1) / SCAN_CHUNK)   // 25
#define NB2 ((N_DST + SCAN_CHUNK - 1) / SCAN_CHUNK)   // 5

// ---- scratch (static device globals; no runtime allocation) ----
__device__ int   g_cnt1[N_MID + SCAN_CHUNK];
__device__ int   g_off1[NB1 * SCAN_CHUNK];
__device__ int   g_bsum1[32];
__device__ int   g_eidx1[E1];
__device__ int   g_slot1[E1];
__device__ int   g_cnt2[N_DST + SCAN_CHUNK];
__device__ int   g_off2[NB2 * SCAN_CHUNK];
__device__ int   g_bsum2[32];
__device__ int   g_eidx2[E2];
__device__ int   g_slot2[E2];
__device__ float g_agg[N_MID * D];
__device__ float g_h[N_MID * D];

// ======================= CSR build (exact R9) =========================
__global__ void zero_all(int* c1, int n1, int* c2, int n2) {
    int i = blockIdx.x * blockDim.x + threadIdx.x;
    if (i < n1) c1[i] = 0;
    if (i < n2) c2[i] = 0;
}

__global__ void hist_slot(const int* __restrict__ col,
                          int* __restrict__ cnt,
                          int* __restrict__ slot, int E) {
    int i = blockIdx.x * blockDim.x + threadIdx.x;
    if (i < E) slot[i] = atomicAdd(&cnt[col[i]], 1);
}

__global__ void __launch_bounds__(256, 4)
scan_partial(const int* __restrict__ cnt, int* __restrict__ off,
             int* __restrict__ bsum) {
    __shared__ int wsum[8];
    const int t = threadIdx.x, lane = t & 31, w = t >> 5;
    const int base = blockIdx.x * SCAN_CHUNK + t * 8;

    int4 a = *(const int4*)(cnt + base);
    int4 b = *(const int4*)(cnt + base + 4);
    int v[8] = {a.x, a.y, a.z, a.w, b.x, b.y, b.z, b.w};
    int s = 0;
    #pragma unroll
    for (int j = 0; j < 8; j++) s += v[j];

    int x = s;
    #pragma unroll
    for (int d = 1; d < 32; d <<= 1) {
        int y = __shfl_up_sync(0xffffffffu, x, d);
        if (lane >= d) x += y;
    }
    if (lane == 31) wsum[w] = x;
    __syncthreads();
    if (t < 8) {
        int ws = wsum[t];
        int p = 0;
        #pragma unroll
        for (int q = 0; q < 8; q++) {
            int val = __shfl_sync(0xffu, ws, q);
            if (q < t) p += val;
        }
        wsum[t] = p;
    }
    __syncthreads();

    int run = (x - s) + wsum[w];
    int o[8];
    #pragma unroll
    for (int j = 0; j < 8; j++) { o[j] = run; run += v[j]; }
    *(int4*)(off + base)     = make_int4(o[0], o[1], o[2], o[3]);
    *(int4*)(off + base + 4) = make_int4(o[4], o[5], o[6], o[7]);
    if (t == 255) bsum[blockIdx.x] = run;
}

__device__ __forceinline__ int warp_bsum_excl(const int* __restrict__ bsum,
                                              int nb) {
    int lane = threadIdx.x & 31;
    int v = (lane < nb) ? bsum[lane] : 0;
    int x = v;
    #pragma unroll
    for (int d = 1; d < 32; d <<= 1) {
        int y = __shfl_up_sync(0xffffffffu, x, d);
        if (lane >= d) x += y;
    }
    return x - v;
}

__global__ void place_scatter(const int* __restrict__ row,
                              const int* __restrict__ col,
                              const int* __restrict__ slot,
                              const int* __restrict__ off,
                              const int* __restrict__ bsum, int nb,
                              int* __restrict__ eidx, int E) {
    int excl = warp_bsum_excl(bsum, nb);
    int i = blockIdx.x * blockDim.x + threadIdx.x;
    if (i < E) {
        int c = col[i];
        int base = off[c] + __shfl_sync(0xffffffffu, excl, c >> 11);
        eidx[base + slot[i]] = row[i];
    }
}

// ======================= aggregation (exact R9) ========================
__global__ void __launch_bounds__(256)
agg_kernel(const float* __restrict__ xsrc,
           const int* __restrict__ off,
           const int* __restrict__ bsum, int nb,
           const int* __restrict__ eidx,
           float* __restrict__ agg, int n) {
    const int excl = warp_bsum_excl(bsum, nb);
    int c    = (blockIdx.x * blockDim.x + threadIdx.x) >> 5;
    int lane = threadIdx.x & 31;
    if (c >= n) return;
    int s = off[c]     + __shfl_sync(0xffffffffu, excl, c >> 11);
    int e = off[c + 1] + __shfl_sync(0xffffffffu, excl, (c + 1) >> 11);

    float4 acc = make_float4(0.f, 0.f, 0.f, 0.f);
    int i = s;
    for (; i + 4 <= e; i += 4) {
        int r0 = eidx[i + 0], r1 = eidx[i + 1];
        int r2 = eidx[i + 2], r3 = eidx[i + 3];
        float4 v0 = ((const float4*)(xsrc + (size_t)r0 * D))[lane];
        float4 v1 = ((const float4*)(xsrc + (size_t)r1 * D))[lane];
        float4 v2 = ((const float4*)(xsrc + (size_t)r2 * D))[lane];
        float4 v3 = ((const float4*)(xsrc + (size_t)r3 * D))[lane];
        acc.x += (v0.x + v1.x) + (v2.x + v3.x);
        acc.y += (v0.y + v1.y) + (v2.y + v3.y);
        acc.z += (v0.z + v1.z) + (v2.z + v3.z);
        acc.w += (v0.w + v1.w) + (v2.w + v3.w);
    }
    for (; i < e; i++) {
        int r = eidx[i];
        float4 v = ((const float4*)(xsrc + (size_t)r * D))[lane];
        acc.x += v.x; acc.y += v.y; acc.z += v.z; acc.w += v.w;
    }
    float invd = (e > s) ? 1.0f / (float)(e - s) : 0.f;
    acc.x *= invd; acc.y *= invd; acc.z *= invd; acc.w *= invd;
    ((float4*)(agg + (size_t)c * D))[lane] = acc;
}

// ===================== mma.sync helpers (sm_80 baseline PTX) ===========
__device__ __forceinline__ uint32_t smem_u32(const void* p) {
    uint32_t a;
    asm("{ .reg .u64 t; cvta.to.shared.u64 t, %1; cvt.u32.u64 %0, t; }"
        : "=r"(a) : "l"(p));
    return a;
}
__device__ __forceinline__ void ldsm_x4(uint32_t& r0, uint32_t& r1,
                                        uint32_t& r2, uint32_t& r3,
                                        uint32_t addr) {
    asm volatile("ldmatrix.sync.aligned.m8n8.x4.shared.b16 {%0,%1,%2,%3}, [%4];"
                 : "=r"(r0), "=r"(r1), "=r"(r2), "=r"(r3) : "r"(addr));
}
__device__ __forceinline__ void ldsm_x2(uint32_t& r0, uint32_t& r1,
                                        uint32_t addr) {
    asm volatile("ldmatrix.sync.aligned.m8n8.x2.shared.b16 {%0,%1}, [%2];"
                 : "=r"(r0), "=r"(r1) : "r"(addr));
}
__device__ __forceinline__ void mma_bf16(float* d, const uint32_t* a,
                                         const uint32_t* b) {
    asm volatile(
        "mma.sync.aligned.m16n8k16.row.col.f32.bf16.bf16.f32 "
        "{%0,%1,%2,%3}, {%4,%5,%6,%7}, {%8,%9}, {%0,%1,%2,%3};"
        : "+f"(d[0]), "+f"(d[1]), "+f"(d[2]), "+f"(d[3])
        : "r"(a[0]), "r"(a[1]), "r"(a[2]), "r"(a[3]), "r"(b[0]), "r"(b[1]));
}

static __device__ __forceinline__ uint32_t pack_hi(float x, float y) {
    unsigned short hx = __bfloat16_as_ushort(__float2bfloat16(x));
    unsigned short hy = __bfloat16_as_ushort(__float2bfloat16(y));
    return (uint32_t)hx | ((uint32_t)hy << 16);
}
static __device__ __forceinline__ uint32_t pack_lo(float x, float y) {
    float rx = x - __bfloat162float(__float2bfloat16(x));
    float ry = y - __bfloat162float(__float2bfloat16(y));
    unsigned short lx = __bfloat16_as_ushort(__float2bfloat16(rx));
    unsigned short ly = __bfloat16_as_ushort(__float2bfloat16(ry));
    return (uint32_t)lx | ((uint32_t)ly << 16);
}

// =============== tensor-core SAGE layer via mma.sync bf16 ==============
// Per CTA: 128-row tile. Two K=128 phases sharing fp32 accumulators:
//   phase A: mean @ Wl^T   phase B: + xdst @ Wr^T
// bf16 split: a·w ≈ ah·wh + ah·wl + al·wh  (err ~1e-5 rel)
// A hi/lo and W hi/lo live in SMEM, 272-byte padded rows (conflict-free
// ldmatrix). Warp w owns N-slab [16w,16w+16), all 128 rows.
#define LDAB2 272                      // padded row bytes (136 bf16)
#define SMA_HI 0
#define SMA_LO (128 * LDAB2)           // 34816
#define SMB_HI (2 * 128 * LDAB2)       // 69632
#define SMB_LO (3 * 128 * LDAB2)       // 104448
#define SM_BIAS (4 * 128 * LDAB2)      // 139264
#define SM_PART (SM_BIAS + 512)        // 139776 (8*128 floats)
#define SM_INVN (SM_PART + 4096)       // 143872
#define MMA_SMEM_BYTES (SM_INVN + 512) // 144384

__device__ __forceinline__ void stage_half(const float* __restrict__ src,
                                           char* sm, int hiOff, int loOff,
                                           int tid, bool guard,
                                           int tileBase, int n) {
    int row = tid >> 1, half = tid & 1;
    int grow = tileBase + row;
    bool valid = !guard || (grow < n);
    const float4* p = (const float4*)(src + (size_t)(guard ? grow : row) * D
                                      + half * 64);
    uint32_t* hi = (uint32_t*)(sm + hiOff + row * LDAB2 + half * 128);
    uint32_t* lo = (uint32_t*)(sm + loOff + row * LDAB2 + half * 128);
    #pragma unroll
    for (int i = 0; i < 16; i++) {
        float4 v = valid ? p[i] : make_float4(0.f, 0.f, 0.f, 0.f);
        hi[2 * i]     = pack_hi(v.x, v.y);
        hi[2 * i + 1] = pack_hi(v.z, v.w);
        lo[2 * i]     = pack_lo(v.x, v.y);
        lo[2 * i + 1] = pack_lo(v.z, v.w);
    }
}

__device__ __forceinline__ void mma_phase(float acc[8][2][4],
                                          uint32_t a_addr0, uint32_t b_addr0) {
    #pragma unroll 1
    for (int ks = 0; ks < 8; ks++) {
        uint32_t k0b = (uint32_t)(ks * 32);          // k0 * 2 bytes
        uint32_t bh0[2], bl0[2], bh1[2], bl1[2];
        ldsm_x2(bh0[0], bh0[1], b_addr0 + SMB_HI + k0b);
        ldsm_x2(bl0[0], bl0[1], b_addr0 + SMB_LO + k0b);
        ldsm_x2(bh1[0], bh1[1], b_addr0 + SMB_HI + 8 * LDAB2 + k0b);
        ldsm_x2(bl1[0], bl1[1], b_addr0 + SMB_LO + 8 * LDAB2 + k0b);
        #pragma unroll
        for (int mf = 0; mf < 8; mf++) {
            uint32_t arow = (uint32_t)(mf * 16 * LDAB2) + k0b;
            uint32_t ah[4], al[4];
            ldsm_x4(ah[0], ah[1], ah[2], ah[3], a_addr0 + SMA_HI + arow);
            ldsm_x4(al[0], al[1], al[2], al[3], a_addr0 + SMA_LO + arow);
            mma_bf16(acc[mf][0], ah, bh0);
            mma_bf16(acc[mf][0], ah, bl0);
            mma_bf16(acc[mf][0], al, bh0);
            mma_bf16(acc[mf][1], ah, bh1);
            mma_bf16(acc[mf][1], ah, bl1);
            mma_bf16(acc[mf][1], al, bh1);
        }
    }
}

template <bool RELU>
__global__ void __launch_bounds__(256, 1)
sage_mma(const float* __restrict__ agg,
         const float* __restrict__ xdst,
         const float* __restrict__ Wl, const float* __restrict__ bl,
         const float* __restrict__ Wr,
         float* __restrict__ out, int n) {
    extern __shared__ char sm[];
    const uint32_t sbase = smem_u32(sm);
    const int tid  = threadIdx.x;
    const int lane = tid & 31;
    const int w    = tid >> 5;
    const int tileBase = blockIdx.x * 128;

    float* sBias = (float*)(sm + SM_BIAS);
    float* sPart = (float*)(sm + SM_PART);
    float* sInv  = (float*)(sm + SM_INVN);

    // ldmatrix lane addresses (byte offsets within an area)
    const uint32_t a_addr0 = sbase +
        (uint32_t)((lane & 15) * LDAB2 + (lane >> 4) * 16);
    const uint32_t b_addr0 = sbase +
        (uint32_t)((w * 16 + (lane & 7)) * LDAB2 + ((lane >> 3) & 1) * 16);

    // ---- phase A staging: A = mean rows, B = Wl ----
    stage_half(agg, sm, SMA_HI, SMA_LO, tid, true,  tileBase, n);
    stage_half(Wl,  sm, SMB_HI, SMB_LO, tid, false, 0, 0);
    if (tid < 128) sBias[tid] = bl[tid];
    __syncthreads();

    float acc[8][2][4];
    #pragma unroll
    for (int mf = 0; mf < 8; mf++)
        #pragma unroll
        for (int nf = 0; nf < 2; nf++)
            acc[mf][nf][0] = acc[mf][nf][1] = acc[mf][nf][2] = acc[mf][nf][3] = 0.f;

    mma_phase(acc, a_addr0, b_addr0);
    __syncthreads();

    // ---- phase B staging: A = xdst rows, B = Wr ----
    stage_half(xdst, sm, SMA_HI, SMA_LO, tid, true,  tileBase, n);
    stage_half(Wr,   sm, SMB_HI, SMB_LO, tid, false, 0, 0);
    __syncthreads();

    mma_phase(acc, a_addr0, b_addr0);

    // ---- epilogue: bias, row sum-of-squares, normalize, store ----
    #pragma unroll
    for (int mf = 0; mf < 8; mf++)
        #pragma unroll
        for (int nf = 0; nf < 2; nf++) {
            int colb = w * 16 + nf * 8 + 2 * (lane & 3);
            float b0 = sBias[colb], b1 = sBias[colb + 1];
            acc[mf][nf][0] += b0; acc[mf][nf][1] += b1;
            acc[mf][nf][2] += b0; acc[mf][nf][3] += b1;
        }

    #pragma unroll
    for (int mf = 0; mf < 8; mf++) {
        float s0 = acc[mf][0][0] * acc[mf][0][0] + acc[mf][0][1] * acc[mf][0][1]
                 + acc[mf][1][0] * acc[mf][1][0] + acc[mf][1][1] * acc[mf][1][1];
        float s1 = acc[mf][0][2] * acc[mf][0][2] + acc[mf][0][3] * acc[mf][0][3]
                 + acc[mf][1][2] * acc[mf][1][2] + acc[mf][1][3] * acc[mf][1][3];
        s0 += __shfl_xor_sync(0xffffffffu, s0, 1);
        s0 += __shfl_xor_sync(0xffffffffu, s0, 2);
        s1 += __shfl_xor_sync(0xffffffffu, s1, 1);
        s1 += __shfl_xor_sync(0xffffffffu, s1, 2);
        if ((lane & 3) == 0) {
            sPart[w * 128 + mf * 16 + (lane >> 2)]     = s0;
            sPart[w * 128 + mf * 16 + (lane >> 2) + 8] = s1;
        }
    }
    __syncthreads();
    if (tid < 128) {
        float tot = 0.f;
        #pragma unroll
        for (int ww = 0; ww < 8; ww++) tot += sPart[ww * 128 + tid];
        sInv[tid] = 1.0f / fmaxf(sqrtf(tot), 1e-12f);
    }
    __syncthreads();

    #pragma unroll
    for (int mf = 0; mf < 8; mf++) {
        int r0l = mf * 16 + (lane >> 2);
        int grow0 = tileBase + r0l;
        int grow1 = grow0 + 8;
        float inv0 = sInv[r0l], inv1 = sInv[r0l + 8];
        #pragma unroll
        for (int nf = 0; nf < 2; nf++) {
            int col = w * 16 + nf * 8 + 2 * (lane & 3);
            float v0 = acc[mf][nf][0] * inv0, v1 = acc[mf][nf][1] * inv0;
            float v2 = acc[mf][nf][2] * inv1, v3 = acc[mf][nf][3] * inv1;
            if (RELU) {
                v0 = fmaxf(v0, 0.f); v1 = fmaxf(v1, 0.f);
                v2 = fmaxf(v2, 0.f); v3 = fmaxf(v3, 0.f);
            }
            if (grow0 < n)
                *(float2*)(out + (size_t)grow0 * D + col) = make_float2(v0, v1);
            if (grow1 < n)
                *(float2*)(out + (size_t)grow1 * D + col) = make_float2(v2, v3);
        }
    }
}

// ---------------------------------------------------------------------
// Launch sequence — EXACT R9 structure; sage kernels -> sage_mma.
// ---------------------------------------------------------------------
extern "C" void kernel_launch(void* const* d_in, const int* in_sizes, int n_in,
                              void* d_out, int out_size) {
    const float* x    = (const float*)d_in[0];
    const float* Wl1  = (const float*)d_in[1];
    const float* bl1  = (const float*)d_in[2];
    const float* Wr1  = (const float*)d_in[3];
    const float* Wl2  = (const float*)d_in[4];
    const float* bl2  = (const float*)d_in[5];
    const float* Wr2  = (const float*)d_in[6];
    const int*   row1 = (const int*)d_in[7];
    const int*   col1 = (const int*)d_in[8];
    const int*   row2 = (const int*)d_in[9];
    const int*   col2 = (const int*)d_in[10];
    float* out = (float*)d_out;

    int *cnt1, *off1, *bsum1, *eidx1, *slot1;
    int *cnt2, *off2, *bsum2, *eidx2, *slot2;
    float *agg, *h;
    cudaGetSymbolAddress((void**)&cnt1, g_cnt1);
    cudaGetSymbolAddress((void**)&off1, g_off1);
    cudaGetSymbolAddress((void**)&bsum1, g_bsum1);
    cudaGetSymbolAddress((void**)&eidx1, g_eidx1);
    cudaGetSymbolAddress((void**)&slot1, g_slot1);
    cudaGetSymbolAddress((void**)&cnt2, g_cnt2);
    cudaGetSymbolAddress((void**)&off2, g_off2);
    cudaGetSymbolAddress((void**)&bsum2, g_bsum2);
    cudaGetSymbolAddress((void**)&eidx2, g_eidx2);
    cudaGetSymbolAddress((void**)&slot2, g_slot2);
    cudaGetSymbolAddress((void**)&agg, g_agg);
    cudaGetSymbolAddress((void**)&h,   g_h);

    cudaFuncSetAttribute(sage_mma<true>,
                         cudaFuncAttributeMaxDynamicSharedMemorySize,
                         MMA_SMEM_BYTES);
    cudaFuncSetAttribute(sage_mma<false>,
                         cudaFuncAttributeMaxDynamicSharedMemorySize,
                         MMA_SMEM_BYTES);

    static cudaStream_t s_side = nullptr;
    static cudaEvent_t  s_ev0  = nullptr, s_ev1 = nullptr;
    if (!s_side) {
        cudaStreamCreateWithFlags(&s_side, cudaStreamNonBlocking);
        cudaEventCreateWithFlags(&s_ev0, cudaEventDisableTiming);
        cudaEventCreateWithFlags(&s_ev1, cudaEventDisableTiming);
    }

    {
        int nmax = N_MID + SCAN_CHUNK;
        zero_all<<<(nmax + 255) / 256, 256>>>(cnt1, N_MID + SCAN_CHUNK,
                                              cnt2, N_DST + SCAN_CHUNK);
    }

    // ---- fork: CSR2 build on side stream ----
    cudaEventRecord(s_ev0, 0);
    cudaStreamWaitEvent(s_side, s_ev0, 0);
    hist_slot<<<(E2 + 255) / 256, 256, 0, s_side>>>(col2, cnt2, slot2, E2);
    scan_partial<<<NB2, 256, 0, s_side>>>(cnt2, off2, bsum2);
    place_scatter<<<(E2 + 255) / 256, 256, 0, s_side>>>(row2, col2, slot2,
                                                        off2, bsum2, NB2,
                                                        eidx2, E2);
    cudaEventRecord(s_ev1, s_side);

    // ---- main: CSR1 build + layer 1 ----
    hist_slot<<<(E1 + 255) / 256, 256>>>(col1, cnt1, slot1, E1);
    scan_partial<<<NB1, 256>>>(cnt1, off1, bsum1);
    place_scatter<<<(E1 + 255) / 256, 256>>>(row1, col1, slot1,
                                             off1, bsum1, NB1, eidx1, E1);
    agg_kernel<<<(N_MID * 32 + 255) / 256, 256>>>(x, off1, bsum1, NB1,
                                                  eidx1, agg, N_MID);
    sage_mma<true><<<(N_MID + 127) / 128, 256, MMA_SMEM_BYTES>>>(
        agg, x, Wl1, bl1, Wr1, h, N_MID);

    // ---- join, layer 2 ----
    cudaStreamWaitEvent(0, s_ev1, 0);
    agg_kernel<<<(N_DST * 32 + 255) / 256, 256>>>(h, off2, bsum2, NB2,
                                                  eidx2, agg, N_DST);
    sage_mma<false><<<(N_DST + 127) / 128, 256, MMA_SMEM_BYTES>>>(
        agg, h, Wl2, bl2, Wr2, out, N_DST);
}